// round 14
// baseline (speedup 1.0000x reference)
#include <cuda_runtime.h>
#include <math.h>
#include <stdint.h>

#define N_PTS 32768
#define D_DIM 128
#define K_CB  1024
#define ND    (N_PTS*D_DIM)
#define MAGICF 12582912.0f        /* 2^23 + 2^22 */

/* ---------------- persistent device scratch -------------------------------- */
__device__ float     g_xn[ND];
__device__ float     g_cn[K_CB*D_DIM];
__device__ float     g_cos[N_PTS*K_CB];     /* 134 MB */
__device__ unsigned  g_cmax[K_CB];          /* per-col max cos (ordered uint) */
__device__ int       g_csE[K_CB];           /* per-col t2 magnitude bound     */
__device__ double    g_u1[K_CB], g_v2[K_CB], g_v3[K_CB];
__device__ float     g_lag[K_CB], g_lalo[K_CB];   /* la grid/lo split         */
__device__ long long g_afix[K_CB];          /* la3 * 2^20 fixed point         */
__device__ unsigned  g_omin, g_omax;
__device__ float     g_mid, g_c1hi, g_c1lo;
__device__ double    g_loss;
__device__ int       g_idx[N_PTS];

/* ---------------- helpers --------------------------------------------------- */
__device__ __forceinline__ unsigned ford(float f) {
    unsigned u = __float_as_uint(f);
    return (u & 0x80000000u) ? ~u : (u | 0x80000000u);
}
__device__ __forceinline__ float funord(unsigned u) {
    return (u & 0x80000000u) ? __uint_as_float(u ^ 0x80000000u)
                             : __uint_as_float(~u);
}
__device__ __forceinline__ float ex2(float x) {
    float r; asm("ex2.approx.f32 %0, %1;" : "=f"(r) : "f"(x)); return r;
}

#define CD_FULL (-288.53900817779268)   /* -log2(e)/0.005 */

/* exact two-float t2 = ((5-5c) - mid) * C1 */
__device__ __forceinline__ void t2_of(float c, float mid, float c1h, float c1l,
                                      float& hi, float& lo) {
    float u  = fmaf(-c, 5.0f, 5.0f) - mid;
    hi = u * c1h;
    lo = fmaf(u, c1h, -hi);
    lo = fmaf(u, c1l, lo);
}

/* t2 split with hi snapped to the 2^-12 grid */
__device__ __forceinline__ void t2grid(float c, float mid, float c1h, float c1l,
                                       float& tg, float& tl) {
    float hi, lo; t2_of(c, mid, c1h, c1l, hi, lo);
    float q = fmaf(hi, 4096.0f, MAGICF);
    float n = q - MAGICF;
    tg = n * 0.000244140625f;            /* exact */
    tl = (hi - tg) + lo;
}

__device__ __forceinline__ long long keyof(float c, float mid, float c1h, float c1l) {
    float hi, lo; t2_of(c, mid, c1h, c1l, hi, lo);
    return __float2ll_rn(hi * 1048576.0f) + __float2ll_rn(lo * 1048576.0f);
}

/* scaled E term: p * 2^(nn - sE), flushing below 2^-126 */
__device__ __forceinline__ float scaledE(float c, float mid, float c1h, float c1l, int sE) {
    float hi, lo; t2_of(c, mid, c1h, c1l, hi, lo);
    float big = hi + MAGICF;
    int   nn  = __float_as_int(big) - __float_as_int(MAGICF);
    float nnf = big - MAGICF;
    float p   = ex2((hi - nnf) + lo);
    int e = nn - sE;
    return (e < -126) ? 0.0f : __int_as_float(__float_as_int(p) + (e << 23));
}

/* DP atomic add of f32 partial with 2^S scale applied via exponent bits */
__device__ __forceinline__ void mergeAtomic(double* dst, float a, int S) {
    if (a > 0.0f) {
        long long b = __double_as_longlong((double)a) + ((long long)S << 52);
        atomicAdd(dst, __longlong_as_double(b));
    }
}

/* ---------------- kernels --------------------------------------------------- */

__global__ void k_init() {
    int i = blockIdx.x * blockDim.x + threadIdx.x;
    if (i < K_CB) { g_cmax[i] = 0u; g_u1[i] = 0.0; g_v2[i] = 0.0; g_v3[i] = 0.0; }
    if (i == 0)   { g_omin = 0xFFFFFFFFu; g_omax = 0u; g_loss = 0.0; }
}

__global__ void k_norm(const float* __restrict__ in, int rows, int isX) {
    int w    = (blockIdx.x * blockDim.x + threadIdx.x) >> 5;
    int lane = threadIdx.x & 31;
    if (w >= rows) return;
    float* out = isX ? g_xn : g_cn;
    const float* r = in + (size_t)w * D_DIM;
    float v0 = r[lane], v1 = r[lane + 32], v2 = r[lane + 64], v3 = r[lane + 96];
    float s = v0 * v0 + v1 * v1 + v2 * v2 + v3 * v3;
    #pragma unroll
    for (int off = 16; off; off >>= 1) s += __shfl_xor_sync(0xFFFFFFFFu, s, off);
    float den = fmaxf(sqrtf(s), 1e-12f);
    float* o = out + (size_t)w * D_DIM;
    o[lane]      = v0 / den;
    o[lane + 32] = v1 / den;
    o[lane + 64] = v2 / den;
    o[lane + 96] = v3 / den;
}

/* cos GEMM + global min/max + smem-reduced per-col max epilogue */
__global__ __launch_bounds__(256, 2) void k_gemm() {
    __shared__ float As[32][132];
    __shared__ float Bs[32][132];
    __shared__ unsigned scm[128];
    int k0 = blockIdx.x * 128;
    int n0 = blockIdx.y * 128;
    int tid = threadIdx.x;
    if (tid < 128) scm[tid] = 0u;
    float acc[8][8];
    #pragma unroll
    for (int i = 0; i < 8; i++)
        #pragma unroll
        for (int j = 0; j < 8; j++) acc[i][j] = 0.0f;

    int ty = tid >> 4, tx = tid & 15;
    for (int d0 = 0; d0 < 128; d0 += 32) {
        #pragma unroll
        for (int i = 0; i < 4; i++) {
            int lin = tid + i * 256;
            int m   = lin >> 3;
            int dq  = lin & 7;
            float4 av = *(const float4*)&g_xn[(size_t)(n0 + m) * 128 + d0 + dq * 4];
            float4 bv = *(const float4*)&g_cn[(size_t)(k0 + m) * 128 + d0 + dq * 4];
            As[dq * 4 + 0][m] = av.x; As[dq * 4 + 1][m] = av.y;
            As[dq * 4 + 2][m] = av.z; As[dq * 4 + 3][m] = av.w;
            Bs[dq * 4 + 0][m] = bv.x; Bs[dq * 4 + 1][m] = bv.y;
            Bs[dq * 4 + 2][m] = bv.z; Bs[dq * 4 + 3][m] = bv.w;
        }
        __syncthreads();
        #pragma unroll
        for (int dd = 0; dd < 32; dd++) {
            float4 a0 = *(const float4*)&As[dd][ty * 8];
            float4 a1 = *(const float4*)&As[dd][ty * 8 + 4];
            float4 b0 = *(const float4*)&Bs[dd][tx * 4];
            float4 b1 = *(const float4*)&Bs[dd][64 + tx * 4];
            float ar[8] = {a0.x,a0.y,a0.z,a0.w,a1.x,a1.y,a1.z,a1.w};
            float br[8] = {b0.x,b0.y,b0.z,b0.w,b1.x,b1.y,b1.z,b1.w};
            #pragma unroll
            for (int i = 0; i < 8; i++)
                #pragma unroll
                for (int j = 0; j < 8; j++) acc[i][j] += ar[i] * br[j];
        }
        __syncthreads();
    }
    float mx = -3.4e38f, mn = 3.4e38f;
    #pragma unroll
    for (int i = 0; i < 8; i++) {
        size_t row = (size_t)(n0 + ty * 8 + i) * 1024;
        float4 v0 = {acc[i][0], acc[i][1], acc[i][2], acc[i][3]};
        float4 v1 = {acc[i][4], acc[i][5], acc[i][6], acc[i][7]};
        *(float4*)&g_cos[row + k0 + tx * 4]      = v0;
        *(float4*)&g_cos[row + k0 + 64 + tx * 4] = v1;
        #pragma unroll
        for (int j = 0; j < 8; j++) {
            mx = fmaxf(mx, acc[i][j]); mn = fminf(mn, acc[i][j]);
        }
    }
    #pragma unroll
    for (int j = 0; j < 8; j++) {
        float cmx = acc[0][j];
        #pragma unroll
        for (int i = 1; i < 8; i++) cmx = fmaxf(cmx, acc[i][j]);
        int cl = (j < 4) ? (tx * 4 + j) : (64 + tx * 4 + (j - 4));
        atomicMax(&scm[cl], ford(cmx));
    }
    #pragma unroll
    for (int off = 16; off; off >>= 1) {
        mx = fmaxf(mx, __shfl_xor_sync(0xFFFFFFFFu, mx, off));
        mn = fminf(mn, __shfl_xor_sync(0xFFFFFFFFu, mn, off));
    }
    __shared__ float smx[8], smn[8];
    if ((tid & 31) == 0) { smx[tid >> 5] = mx; smn[tid >> 5] = mn; }
    __syncthreads();
    if (tid == 0) {
        float bmx = smx[0], bmn = smn[0];
        for (int i = 1; i < 8; i++) { bmx = fmaxf(bmx, smx[i]); bmn = fminf(bmn, smn[i]); }
        atomicMax(&g_omax, ford(bmx));
        atomicMin(&g_omin, ford(bmn));
    }
    if (tid < 128) atomicMax(&g_cmax[k0 + tid], scm[tid]);
}

/* fused: mid/c1 constants + per-column t2 bound (one block, 1024 thr) */
__global__ void k_pre() {
    __shared__ float sc[3];
    if (threadIdx.x == 0) {
        float cmin = funord(g_omin), cmax = funord(g_omax);
        float dmax = fmaf(-cmin, 5.0f, 5.0f);
        float dmin = fmaf(-cmax, 5.0f, 5.0f);
        float mid  = (dmax + dmin) / 2.0f;
        float amp  = fmaxf(dmax - mid + 1e-5f, 1e-5f);
        double c1  = CD_FULL / (double)amp;
        float hi = (float)c1;
        g_mid = mid; g_c1hi = hi; g_c1lo = (float)(c1 - (double)hi);
        sc[0] = mid; sc[1] = hi; sc[2] = (float)(c1 - (double)hi);
    }
    __syncthreads();
    int k = threadIdx.x;
    float c = funord(g_cmax[k]);
    float hi, lo; t2_of(c, sc[0], sc[1], sc[2], hi, lo);
    float big = hi + MAGICF;
    g_csE[k] = __float_as_int(big) - __float_as_int(MAGICF);
}

/* u1[k] = sum_n E — scaled f32 accumulation, DP merge; 64 rows/block */
__global__ __launch_bounds__(256) void k_u1() {
    int t  = threadIdx.x;
    int r0 = blockIdx.x * 64;
    float mid = g_mid, c1h = g_c1hi, c1l = g_c1lo;
    int e0 = g_csE[4*t], e1 = g_csE[4*t+1], e2 = g_csE[4*t+2], e3 = g_csE[4*t+3];
    float a0 = 0, a1 = 0, a2 = 0, a3 = 0;
    #pragma unroll 4
    for (int r = 0; r < 64; r++) {
        float4 v = *(const float4*)(g_cos + (size_t)(r0 + r) * 1024 + 4 * t);
        a0 += scaledE(v.x, mid, c1h, c1l, e0);
        a1 += scaledE(v.y, mid, c1h, c1l, e1);
        a2 += scaledE(v.z, mid, c1h, c1l, e2);
        a3 += scaledE(v.w, mid, c1h, c1l, e3);
    }
    mergeAtomic(&g_u1[4*t+0], a0, e0);
    mergeAtomic(&g_u1[4*t+1], a1, e1);
    mergeAtomic(&g_u1[4*t+2], a2, e2);
    mergeAtomic(&g_u1[4*t+3], a3, e3);
}

/* la[k] = -10 - log2(u[k]); sel picks buffer in device code */
__global__ void k_la(int sel, int final_) {
    int k = threadIdx.x;
    const double* u = (sel == 1) ? g_u1 : (sel == 2) ? g_v2 : g_v3;
    double la = -10.0 - log2(u[k]);
    if (final_) {
        g_afix[k] = llround(la * 1048576.0);
        return;
    }
    double gq = rint(la * 4096.0) * (1.0 / 4096.0);
    g_lag[k]  = (float)gq;
    g_lalo[k] = (float)(la - gq);
}

/* FUSED row pass: per row compute lb = -15 - LSE_k(t2+la) (exact grid max,
   round-12 semantics), then immediately accumulate v[k] += 2^(t2+lb) as
   EXACT doubles (integer exponent splice, zero DP arithmetic) into
   bank-permuted shared double accumulators.  One cos read serves both. */
__global__ __launch_bounds__(256) void k_lbv(int pass) {
    __shared__ float  s_lag[1024], s_lalo[1024];
    __shared__ double sacc[1024];               /* permuted: (k&3)*256+(k>>2) */
    double* vout = (pass == 1) ? g_v2 : g_v3;
    int tid = threadIdx.x;
    for (int i = tid; i < 1024; i += 256) {
        s_lag[i] = g_lag[i]; s_lalo[i] = g_lalo[i]; sacc[i] = 0.0;
    }
    __syncthreads();
    int warp = tid >> 5, lane = tid & 31;
    float mid = g_mid, c1h = g_c1hi, c1l = g_c1lo;
    int n0 = blockIdx.x * 32 + warp * 4;
    for (int r = 0; r < 4; r++) {
        int n = n0 + r;
        const float4* row = (const float4*)(g_cos + (size_t)n * 1024);
        float c[32];
        #pragma unroll
        for (int j = 0; j < 8; j++) {
            float4 v = row[lane + 32 * j];
            c[4*j+0] = v.x; c[4*j+1] = v.y; c[4*j+2] = v.z; c[4*j+3] = v.w;
        }
        /* pass 1: exact max of grid keys */
        float mkg = -1e30f;
        #pragma unroll
        for (int j = 0; j < 8; j++) {
            #pragma unroll
            for (int m = 0; m < 4; m++) {
                int k = 4*lane + 128*j + m;
                float tg, tl; t2grid(c[4*j+m], mid, c1h, c1l, tg, tl);
                mkg = fmaxf(mkg, tg + s_lag[k]);
            }
        }
        #pragma unroll
        for (int off = 16; off; off >>= 1)
            mkg = fmaxf(mkg, __shfl_xor_sync(0xFFFFFFFFu, mkg, off));
        /* pass 2: LSE sum (kg - mkg exact: both grid multiples) */
        float sA = 0.0f, sB = 0.0f;
        #pragma unroll
        for (int j = 0; j < 8; j++) {
            #pragma unroll
            for (int m = 0; m < 4; m++) {
                int k = 4*lane + 128*j + m;
                float tg, tl; t2grid(c[4*j+m], mid, c1h, c1l, tg, tl);
                float kg = tg + s_lag[k];
                float kl = tl + s_lalo[k];
                float term = ex2((kg - mkg) + kl);
                if (m & 1) sB += term; else sA += term;
            }
        }
        float s = sA + sB;
        #pragma unroll
        for (int off = 16; off; off >>= 1) s += __shfl_xor_sync(0xFFFFFFFFu, s, off);
        float lbg, lblo;
        if (lane == 0) {
            double lb = -15.0 - ((double)mkg + log2((double)s));
            double gq = rint(lb * 4096.0) * (1.0 / 4096.0);
            lbg  = (float)gq;
            lblo = (float)(lb - gq);
        }
        lbg  = __shfl_sync(0xFFFFFFFFu, lbg, 0);
        lblo = __shfl_sync(0xFFFFFFFFu, lblo, 0);
        /* phase 2: v[k] += 2^(t2 + lb) as exact double (exponent splice) */
        #pragma unroll
        for (int j = 0; j < 8; j++) {
            #pragma unroll
            for (int m = 0; m < 4; m++) {
                int k = 4*lane + 128*j + m;
                float tg, tl; t2grid(c[4*j+m], mid, c1h, c1l, tg, tl);
                float f   = tg + lbg;            /* exact grid add */
                float big = f + MAGICF;
                int   nn  = __float_as_int(big) - __float_as_int(MAGICF);
                float fr  = (f - (big - MAGICF)) + (tl + lblo);
                float p   = ex2(fr);             /* in [0.70, 1.42) */
                unsigned long long eb =
                    ((unsigned long long)__float_as_uint(p) << 29) +
                    ((unsigned long long)(unsigned)(896 + nn) << 52);
                int pk = (k & 3) * 256 + (k >> 2);   /* bank permutation */
                atomicAdd(&sacc[pk], __longlong_as_double((long long)eb));
            }
        }
    }
    __syncthreads();
    for (int i = tid; i < 1024; i += 256)
        atomicAdd(&vout[i], sacc[(i & 3) * 256 + (i >> 2)]);
}

/* argmax (s64 fixed-point keys) + per-row lse + loss; warp per row */
__global__ __launch_bounds__(256) void k_argmax() {
    __shared__ long long sA[1024];
    __shared__ double lpart[8];
    int tid = threadIdx.x;
    for (int i = tid; i < 1024; i += 256) sA[i] = g_afix[i];
    __syncthreads();
    int warp = tid >> 5, lane = tid & 31;
    float mid = g_mid, c1h = g_c1hi, c1l = g_c1lo;
    int n0 = blockIdx.x * 32 + warp * 4;
    double lsum = 0.0;
    for (int r = 0; r < 4; r++) {
        int n = n0 + r;
        const float4* row = (const float4*)(g_cos + (size_t)n * 1024);
        long long bkey = 0x8000000000000000LL;
        int bk = 0;
        float c[32];
        float cmx = -3.4e38f;
        #pragma unroll
        for (int j = 0; j < 8; j++) {
            float4 v = row[lane + 32 * j];
            int kb = 4 * lane + 128 * j;
            c[4*j+0] = v.x; c[4*j+1] = v.y; c[4*j+2] = v.z; c[4*j+3] = v.w;
            #pragma unroll
            for (int mI = 0; mI < 4; mI++) {
                float cv = c[4*j+mI];
                cmx = fmaxf(cmx, cv);
                long long key = keyof(cv, mid, c1h, c1l) + sA[kb + mI];
                int kk = kb + mI;
                if (key > bkey || (key == bkey && kk < bk)) { bkey = key; bk = kk; }
            }
        }
        #pragma unroll
        for (int off = 16; off; off >>= 1) {
            long long ov = __shfl_down_sync(0xFFFFFFFFu, bkey, off);
            int       ok = __shfl_down_sync(0xFFFFFFFFu, bk,   off);
            if (ov > bkey || (ov == bkey && ok < bk)) { bkey = ov; bk = ok; }
        }
        bk = __shfl_sync(0xFFFFFFFFu, bk, 0);
        #pragma unroll
        for (int off = 16; off; off >>= 1)
            cmx = fmaxf(cmx, __shfl_xor_sync(0xFFFFFFFFu, cmx, off));
        float s = 0.0f;
        #pragma unroll
        for (int j = 0; j < 32; j++)
            s += ex2((c[j] - cmx) * 7.2134752044448170f);   /* 5*log2(e) */
        #pragma unroll
        for (int off = 16; off; off >>= 1) s += __shfl_xor_sync(0xFFFFFFFFu, s, off);
        if (lane == 0) {
            g_idx[n] = bk;
            float lse = cmx * 5.0f + logf(s);
            float li  = ((const float*)row)[bk] * 5.0f;
            lsum += (double)(lse - li);
        }
    }
    if (lane == 0) lpart[warp] = lsum;
    __syncthreads();
    if (tid == 0) {
        double t = 0.0;
        for (int i = 0; i < 8; i++) t += lpart[i];
        atomicAdd(&g_loss, t);
    }
}

/* x_q gather, vectorized: 4 floats per thread */
__global__ void k_out4(const float* __restrict__ codebook,
                       float4* __restrict__ out4, int nvec) {
    int i = blockIdx.x * blockDim.x + threadIdx.x;
    if (i >= nvec) return;
    int n   = i >> 5;            /* 32 float4 per row */
    int col = (i & 31) * 4;
    const float* src = codebook + (size_t)g_idx[n] * 128 + col;
    out4[i] = make_float4(src[0], src[1], src[2], src[3]);
}

/* tail: loss + indices (+ scalar fallback for any unaligned remainder) */
__global__ void k_tail(const float* __restrict__ codebook,
                       float* __restrict__ out, int start, int out_size) {
    int i = start + blockIdx.x * blockDim.x + threadIdx.x;
    if (i >= out_size) return;
    if (i < ND) {
        int n = i >> 7;
        out[i] = codebook[(size_t)g_idx[n] * 128 + (i & 127)];
    } else if (i == ND) {
        out[i] = (float)(g_loss / 32768.0);
    } else {
        int j = i - ND - 1;
        out[i] = (j < N_PTS) ? (float)g_idx[j] : 0.0f;
    }
}

/* ---------------- launch ---------------------------------------------------- */
extern "C" void kernel_launch(void* const* d_in, const int* in_sizes, int n_in,
                              void* d_out, int out_size) {
    const float* x  = (const float*)d_in[0];
    const float* cb = (const float*)d_in[1];
    if (n_in >= 2 && in_sizes[0] == K_CB * D_DIM && in_sizes[1] == ND) {
        const float* t = x; x = cb; cb = t;
    }
    float* out = (float*)d_out;

    k_init<<<(K_CB + 255) / 256, 256>>>();
    k_norm<<<(K_CB * 32 + 255) / 256, 256>>>(cb, K_CB, 0);
    k_norm<<<(N_PTS * 32 + 255) / 256, 256>>>(x, N_PTS, 1);

    dim3 ggrid(K_CB / 128, N_PTS / 128);
    k_gemm<<<ggrid, 256>>>();
    k_pre<<<1, 1024>>>();

    k_u1<<<N_PTS / 64, 256>>>();        /* u1                        */
    k_la<<<1, 1024>>>(1, 0);            /* la1                       */
    k_lbv<<<N_PTS / 32, 256>>>(1);      /* lb1 + v2 fused            */
    k_la<<<1, 1024>>>(2, 0);            /* la2                       */
    k_lbv<<<N_PTS / 32, 256>>>(2);      /* lb2 + v3 fused            */
    k_la<<<1, 1024>>>(3, 1);            /* afix = la3 * 2^20         */

    k_argmax<<<N_PTS / 32, 256>>>();

    /* vectorized gather for the x_q segment, scalar tail for the rest */
    int nvec = (out_size < ND ? out_size : ND) / 4;
    if (nvec > 0)
        k_out4<<<(nvec + 255) / 256, 256>>>(cb, (float4*)out, nvec);
    int start = nvec * 4;
    int rem = out_size - start;
    if (rem > 0)
        k_tail<<<(rem + 255) / 256, 256>>>(cb, out, start, out_size);
}

// round 15
// speedup vs baseline: 1.2021x; 1.2021x over previous
#include <cuda_runtime.h>
#include <math.h>
#include <stdint.h>

#define N_PTS 32768
#define D_DIM 128
#define K_CB  1024
#define ND    (N_PTS*D_DIM)
#define MAGICF 12582912.0f        /* 2^23 + 2^22 */

/* ---------------- persistent device scratch -------------------------------- */
__device__ float     g_xn[ND];
__device__ float     g_cn[K_CB*D_DIM];
__device__ float     g_cos[N_PTS*K_CB];     /* 134 MB */
__device__ unsigned  g_cmax[K_CB];          /* per-col max cos (ordered uint) */
__device__ int       g_csE[K_CB];           /* per-col t2 magnitude bound     */
__device__ double    g_u1[K_CB], g_v2[K_CB], g_v3[K_CB];
__device__ float     g_lag[K_CB], g_lalo[K_CB];   /* la grid/lo split         */
__device__ float     g_lbg[N_PTS], g_lblo[N_PTS]; /* lb grid/lo split         */
__device__ long long g_afix[K_CB];          /* la3 * 2^20 fixed point         */
__device__ unsigned  g_omin, g_omax;
__device__ float     g_mid, g_c1hi, g_c1lo;
__device__ double    g_loss;
__device__ int       g_idx[N_PTS];

/* ---------------- helpers --------------------------------------------------- */
__device__ __forceinline__ unsigned ford(float f) {
    unsigned u = __float_as_uint(f);
    return (u & 0x80000000u) ? ~u : (u | 0x80000000u);
}
__device__ __forceinline__ float funord(unsigned u) {
    return (u & 0x80000000u) ? __uint_as_float(u ^ 0x80000000u)
                             : __uint_as_float(~u);
}
__device__ __forceinline__ float ex2(float x) {
    float r; asm("ex2.approx.f32 %0, %1;" : "=f"(r) : "f"(x)); return r;
}
__device__ __forceinline__ void prefetchL2(const void* p) {
    asm volatile("prefetch.global.L2 [%0];" :: "l"(p));
}

#define CD_FULL (-288.53900817779268)   /* -log2(e)/0.005 */

/* exact two-float t2 = ((5-5c) - mid) * C1 */
__device__ __forceinline__ void t2_of(float c, float mid, float c1h, float c1l,
                                      float& hi, float& lo) {
    float u  = fmaf(-c, 5.0f, 5.0f) - mid;
    hi = u * c1h;
    lo = fmaf(u, c1h, -hi);
    lo = fmaf(u, c1l, lo);
}

/* t2 split with hi snapped to the 2^-12 grid */
__device__ __forceinline__ void t2grid(float c, float mid, float c1h, float c1l,
                                       float& tg, float& tl) {
    float hi, lo; t2_of(c, mid, c1h, c1l, hi, lo);
    float q = fmaf(hi, 4096.0f, MAGICF);
    float n = q - MAGICF;
    tg = n * 0.000244140625f;            /* exact */
    tl = (hi - tg) + lo;
}

__device__ __forceinline__ long long keyof(float c, float mid, float c1h, float c1l) {
    float hi, lo; t2_of(c, mid, c1h, c1l, hi, lo);
    return __float2ll_rn(hi * 1048576.0f) + __float2ll_rn(lo * 1048576.0f);
}

/* scaled E term: p * 2^(nn - sE), flushing below 2^-126 */
__device__ __forceinline__ float scaledE(float c, float mid, float c1h, float c1l, int sE) {
    float hi, lo; t2_of(c, mid, c1h, c1l, hi, lo);
    float big = hi + MAGICF;
    int   nn  = __float_as_int(big) - __float_as_int(MAGICF);
    float nnf = big - MAGICF;
    float p   = ex2((hi - nnf) + lo);
    int e = nn - sE;
    return (e < -126) ? 0.0f : __int_as_float(__float_as_int(p) + (e << 23));
}

/* weighted scaled term: 2^(t2 + w - sE) with w given as grid/lo pair */
__device__ __forceinline__ float scaledEw(float c, float mid, float c1h, float c1l,
                                          float wg, float wl, int sE) {
    float tg, tl; t2grid(c, mid, c1h, c1l, tg, tl);
    float f   = tg + wg;                 /* exact: both 2^-12 grid multiples */
    float big = f + MAGICF;
    int   ei  = __float_as_int(big) - __float_as_int(MAGICF);
    float fnf = big - MAGICF;
    float p   = ex2((f - fnf) + (tl + wl));
    int e = ei - sE;
    return (e < -126) ? 0.0f : __int_as_float(__float_as_int(p) + (e << 23));
}

/* DP atomic add of f32 partial with 2^S scale applied via exponent bits */
__device__ __forceinline__ void mergeAtomic(double* dst, float a, int S) {
    if (a > 0.0f) {
        long long b = __double_as_longlong((double)a) + ((long long)S << 52);
        atomicAdd(dst, __longlong_as_double(b));
    }
}

/* ---------------- kernels --------------------------------------------------- */

__global__ void k_init() {
    int i = blockIdx.x * blockDim.x + threadIdx.x;
    if (i < K_CB) { g_cmax[i] = 0u; g_u1[i] = 0.0; g_v2[i] = 0.0; g_v3[i] = 0.0; }
    if (i == 0)   { g_omin = 0xFFFFFFFFu; g_omax = 0u; g_loss = 0.0; }
}

__global__ void k_norm(const float* __restrict__ in, int rows, int isX) {
    int w    = (blockIdx.x * blockDim.x + threadIdx.x) >> 5;
    int lane = threadIdx.x & 31;
    if (w >= rows) return;
    float* out = isX ? g_xn : g_cn;
    const float* r = in + (size_t)w * D_DIM;
    float v0 = r[lane], v1 = r[lane + 32], v2 = r[lane + 64], v3 = r[lane + 96];
    float s = v0 * v0 + v1 * v1 + v2 * v2 + v3 * v3;
    #pragma unroll
    for (int off = 16; off; off >>= 1) s += __shfl_xor_sync(0xFFFFFFFFu, s, off);
    float den = fmaxf(sqrtf(s), 1e-12f);
    float* o = out + (size_t)w * D_DIM;
    o[lane]      = v0 / den;
    o[lane + 32] = v1 / den;
    o[lane + 64] = v2 / den;
    o[lane + 96] = v3 / den;
}

/* cos GEMM + global min/max + smem-reduced per-col max epilogue */
__global__ __launch_bounds__(256, 2) void k_gemm() {
    __shared__ float As[32][132];
    __shared__ float Bs[32][132];
    __shared__ unsigned scm[128];
    int k0 = blockIdx.x * 128;
    int n0 = blockIdx.y * 128;
    int tid = threadIdx.x;
    if (tid < 128) scm[tid] = 0u;
    float acc[8][8];
    #pragma unroll
    for (int i = 0; i < 8; i++)
        #pragma unroll
        for (int j = 0; j < 8; j++) acc[i][j] = 0.0f;

    int ty = tid >> 4, tx = tid & 15;
    for (int d0 = 0; d0 < 128; d0 += 32) {
        #pragma unroll
        for (int i = 0; i < 4; i++) {
            int lin = tid + i * 256;
            int m   = lin >> 3;
            int dq  = lin & 7;
            float4 av = *(const float4*)&g_xn[(size_t)(n0 + m) * 128 + d0 + dq * 4];
            float4 bv = *(const float4*)&g_cn[(size_t)(k0 + m) * 128 + d0 + dq * 4];
            As[dq * 4 + 0][m] = av.x; As[dq * 4 + 1][m] = av.y;
            As[dq * 4 + 2][m] = av.z; As[dq * 4 + 3][m] = av.w;
            Bs[dq * 4 + 0][m] = bv.x; Bs[dq * 4 + 1][m] = bv.y;
            Bs[dq * 4 + 2][m] = bv.z; Bs[dq * 4 + 3][m] = bv.w;
        }
        __syncthreads();
        #pragma unroll
        for (int dd = 0; dd < 32; dd++) {
            float4 a0 = *(const float4*)&As[dd][ty * 8];
            float4 a1 = *(const float4*)&As[dd][ty * 8 + 4];
            float4 b0 = *(const float4*)&Bs[dd][tx * 4];
            float4 b1 = *(const float4*)&Bs[dd][64 + tx * 4];
            float ar[8] = {a0.x,a0.y,a0.z,a0.w,a1.x,a1.y,a1.z,a1.w};
            float br[8] = {b0.x,b0.y,b0.z,b0.w,b1.x,b1.y,b1.z,b1.w};
            #pragma unroll
            for (int i = 0; i < 8; i++)
                #pragma unroll
                for (int j = 0; j < 8; j++) acc[i][j] += ar[i] * br[j];
        }
        __syncthreads();
    }
    float mx = -3.4e38f, mn = 3.4e38f;
    #pragma unroll
    for (int i = 0; i < 8; i++) {
        size_t row = (size_t)(n0 + ty * 8 + i) * 1024;
        float4 v0 = {acc[i][0], acc[i][1], acc[i][2], acc[i][3]};
        float4 v1 = {acc[i][4], acc[i][5], acc[i][6], acc[i][7]};
        *(float4*)&g_cos[row + k0 + tx * 4]      = v0;
        *(float4*)&g_cos[row + k0 + 64 + tx * 4] = v1;
        #pragma unroll
        for (int j = 0; j < 8; j++) {
            mx = fmaxf(mx, acc[i][j]); mn = fminf(mn, acc[i][j]);
        }
    }
    #pragma unroll
    for (int j = 0; j < 8; j++) {
        float cmx = acc[0][j];
        #pragma unroll
        for (int i = 1; i < 8; i++) cmx = fmaxf(cmx, acc[i][j]);
        int cl = (j < 4) ? (tx * 4 + j) : (64 + tx * 4 + (j - 4));
        atomicMax(&scm[cl], ford(cmx));
    }
    #pragma unroll
    for (int off = 16; off; off >>= 1) {
        mx = fmaxf(mx, __shfl_xor_sync(0xFFFFFFFFu, mx, off));
        mn = fminf(mn, __shfl_xor_sync(0xFFFFFFFFu, mn, off));
    }
    __shared__ float smx[8], smn[8];
    if ((tid & 31) == 0) { smx[tid >> 5] = mx; smn[tid >> 5] = mn; }
    __syncthreads();
    if (tid == 0) {
        float bmx = smx[0], bmn = smn[0];
        for (int i = 1; i < 8; i++) { bmx = fmaxf(bmx, smx[i]); bmn = fminf(bmn, smn[i]); }
        atomicMax(&g_omax, ford(bmx));
        atomicMin(&g_omin, ford(bmn));
    }
    if (tid < 128) atomicMax(&g_cmax[k0 + tid], scm[tid]);
}

/* fused: mid/c1 constants + per-column t2 bound (one block, 1024 thr) */
__global__ void k_pre() {
    __shared__ float sc[3];
    if (threadIdx.x == 0) {
        float cmin = funord(g_omin), cmax = funord(g_omax);
        float dmax = fmaf(-cmin, 5.0f, 5.0f);
        float dmin = fmaf(-cmax, 5.0f, 5.0f);
        float mid  = (dmax + dmin) / 2.0f;
        float amp  = fmaxf(dmax - mid + 1e-5f, 1e-5f);
        double c1  = CD_FULL / (double)amp;
        float hi = (float)c1;
        g_mid = mid; g_c1hi = hi; g_c1lo = (float)(c1 - (double)hi);
        sc[0] = mid; sc[1] = hi; sc[2] = (float)(c1 - (double)hi);
    }
    __syncthreads();
    int k = threadIdx.x;
    float c = funord(g_cmax[k]);
    float hi, lo; t2_of(c, sc[0], sc[1], sc[2], hi, lo);
    float big = hi + MAGICF;
    g_csE[k] = __float_as_int(big) - __float_as_int(MAGICF);
}

/* u1[k] = sum_n E — scaled f32 accumulation, DP merge; 64 rows/block */
__global__ __launch_bounds__(256) void k_u1() {
    int t  = threadIdx.x;
    int r0 = blockIdx.x * 64;
    float mid = g_mid, c1h = g_c1hi, c1l = g_c1lo;
    int e0 = g_csE[4*t], e1 = g_csE[4*t+1], e2 = g_csE[4*t+2], e3 = g_csE[4*t+3];
    float a0 = 0, a1 = 0, a2 = 0, a3 = 0;
    #pragma unroll 4
    for (int r = 0; r < 64; r++) {
        float4 v = *(const float4*)(g_cos + (size_t)(r0 + r) * 1024 + 4 * t);
        a0 += scaledE(v.x, mid, c1h, c1l, e0);
        a1 += scaledE(v.y, mid, c1h, c1l, e1);
        a2 += scaledE(v.z, mid, c1h, c1l, e2);
        a3 += scaledE(v.w, mid, c1h, c1l, e3);
    }
    mergeAtomic(&g_u1[4*t+0], a0, e0);
    mergeAtomic(&g_u1[4*t+1], a1, e1);
    mergeAtomic(&g_u1[4*t+2], a2, e2);
    mergeAtomic(&g_u1[4*t+3], a3, e3);
}

/* la[k] = -10 - log2(u[k]); sel picks buffer in device code */
__global__ void k_la(int sel, int final_) {
    int k = threadIdx.x;
    const double* u = (sel == 1) ? g_u1 : (sel == 2) ? g_v2 : g_v3;
    double la = -10.0 - log2(u[k]);
    if (final_) {
        g_afix[k] = llround(la * 1048576.0);
        return;
    }
    double gq = rint(la * 4096.0) * (1.0 / 4096.0);
    g_lag[k]  = (float)gq;
    g_lalo[k] = (float)(la - gq);
}

/* lb[n] = -15 - LSE_k(t2 + la[k]); warp per row.
   pass 1 = cheap upper-bound max (t2_of only) snapped UP with +2 grid-ulp
   guard; pass 2 exact grid subs.  L2 prefetch of next row. */
__global__ __launch_bounds__(256) void k_lb() {
    __shared__ float s_lag[1024], s_lalo[1024];
    int tid = threadIdx.x;
    for (int i = tid; i < 1024; i += 256) { s_lag[i] = g_lag[i]; s_lalo[i] = g_lalo[i]; }
    __syncthreads();
    int warp = tid >> 5, lane = tid & 31;
    float mid = g_mid, c1h = g_c1hi, c1l = g_c1lo;
    int n0 = blockIdx.x * 32 + warp * 4;
    for (int r = 0; r < 4; r++) {
        int n = n0 + r;
        const float4* row = (const float4*)(g_cos + (size_t)n * 1024);
        if (r < 3) prefetchL2((const char*)(row + 256) + lane * 128);
        float c[32];
        #pragma unroll
        for (int j = 0; j < 8; j++) {
            float4 v = row[lane + 32 * j];
            c[4*j+0] = v.x; c[4*j+1] = v.y; c[4*j+2] = v.z; c[4*j+3] = v.w;
        }
        /* pass 1: cheap upper estimate of key max */
        float m1 = -1e30f;
        #pragma unroll
        for (int j = 0; j < 8; j++) {
            #pragma unroll
            for (int m = 0; m < 4; m++) {
                int k = 4*lane + 128*j + m;
                float hi, lo; t2_of(c[4*j+m], mid, c1h, c1l, hi, lo);
                m1 = fmaxf(m1, hi + s_lag[k]);
            }
        }
        #pragma unroll
        for (int off = 16; off; off >>= 1)
            m1 = fmaxf(m1, __shfl_xor_sync(0xFFFFFFFFu, m1, off));
        /* snap up to grid with +2 ulp guard -> mq >= every true key */
        float qb = fmaf(m1, 4096.0f, MAGICF);
        int   nq = (__float_as_int(qb) - __float_as_int(MAGICF)) + 2;
        float mq = (float)nq * 0.000244140625f;
        /* pass 2: sum of 2^(key - mq); kg-mq exact (grid multiples) */
        float sA = 0.0f, sB = 0.0f;
        #pragma unroll
        for (int j = 0; j < 8; j++) {
            #pragma unroll
            for (int m = 0; m < 4; m++) {
                int k = 4*lane + 128*j + m;
                float tg, tl; t2grid(c[4*j+m], mid, c1h, c1l, tg, tl);
                float kg = tg + s_lag[k];
                float kl = tl + s_lalo[k];
                float term = ex2((kg - mq) + kl);
                if (m & 1) sB += term; else sA += term;
            }
        }
        float s = sA + sB;
        #pragma unroll
        for (int off = 16; off; off >>= 1) s += __shfl_xor_sync(0xFFFFFFFFu, s, off);
        if (lane == 0) {
            double lb = -15.0 - ((double)mq + log2((double)s));
            double gq = rint(lb * 4096.0) * (1.0 / 4096.0);
            g_lbg[n]  = (float)gq;
            g_lblo[n] = (float)(lb - gq);
        }
    }
}

/* v[k] = sum_n 2^(t2 + lb[n]) — col-strided scaled f32; 64 rows/block */
__global__ __launch_bounds__(256) void k_v(int pass) {
    __shared__ float s_lbg[64], s_lblo[64];
    __shared__ int   s_wB;
    double* vout = (pass == 1) ? g_v2 : g_v3;
    int t  = threadIdx.x;
    int r0 = blockIdx.x * 64;
    if (t < 64) { s_lbg[t] = g_lbg[r0 + t]; s_lblo[t] = g_lblo[r0 + t]; }
    __syncthreads();
    if (t == 0) {
        float m = s_lbg[0];
        for (int i = 1; i < 64; i++) m = fmaxf(m, s_lbg[i]);
        s_wB = (int)ceilf(m) + 1;
    }
    __syncthreads();
    int wB = s_wB;
    float mid = g_mid, c1h = g_c1hi, c1l = g_c1lo;
    int e0 = g_csE[4*t] + wB, e1 = g_csE[4*t+1] + wB,
        e2 = g_csE[4*t+2] + wB, e3 = g_csE[4*t+3] + wB;
    float a0 = 0, a1 = 0, a2 = 0, a3 = 0;
    #pragma unroll 4
    for (int r = 0; r < 64; r++) {
        float4 v = *(const float4*)(g_cos + (size_t)(r0 + r) * 1024 + 4 * t);
        float wg = s_lbg[r], wl = s_lblo[r];
        a0 += scaledEw(v.x, mid, c1h, c1l, wg, wl, e0);
        a1 += scaledEw(v.y, mid, c1h, c1l, wg, wl, e1);
        a2 += scaledEw(v.z, mid, c1h, c1l, wg, wl, e2);
        a3 += scaledEw(v.w, mid, c1h, c1l, wg, wl, e3);
    }
    mergeAtomic(&vout[4*t+0], a0, e0);
    mergeAtomic(&vout[4*t+1], a1, e1);
    mergeAtomic(&vout[4*t+2], a2, e2);
    mergeAtomic(&vout[4*t+3], a3, e3);
}

/* argmax (s64 fixed-point keys) + per-row lse + loss; warp per row */
__global__ __launch_bounds__(256) void k_argmax() {
    __shared__ long long sA[1024];
    __shared__ double lpart[8];
    int tid = threadIdx.x;
    for (int i = tid; i < 1024; i += 256) sA[i] = g_afix[i];
    __syncthreads();
    int warp = tid >> 5, lane = tid & 31;
    float mid = g_mid, c1h = g_c1hi, c1l = g_c1lo;
    int n0 = blockIdx.x * 32 + warp * 4;
    double lsum = 0.0;
    for (int r = 0; r < 4; r++) {
        int n = n0 + r;
        const float4* row = (const float4*)(g_cos + (size_t)n * 1024);
        if (r < 3) prefetchL2((const char*)(row + 256) + lane * 128);
        long long bkey = 0x8000000000000000LL;
        int bk = 0;
        float c[32];
        float cmx = -3.4e38f;
        #pragma unroll
        for (int j = 0; j < 8; j++) {
            float4 v = row[lane + 32 * j];
            int kb = 4 * lane + 128 * j;
            c[4*j+0] = v.x; c[4*j+1] = v.y; c[4*j+2] = v.z; c[4*j+3] = v.w;
            #pragma unroll
            for (int mI = 0; mI < 4; mI++) {
                float cv = c[4*j+mI];
                cmx = fmaxf(cmx, cv);
                long long key = keyof(cv, mid, c1h, c1l) + sA[kb + mI];
                int kk = kb + mI;
                if (key > bkey || (key == bkey && kk < bk)) { bkey = key; bk = kk; }
            }
        }
        #pragma unroll
        for (int off = 16; off; off >>= 1) {
            long long ov = __shfl_down_sync(0xFFFFFFFFu, bkey, off);
            int       ok = __shfl_down_sync(0xFFFFFFFFu, bk,   off);
            if (ov > bkey || (ov == bkey && ok < bk)) { bkey = ov; bk = ok; }
        }
        bk = __shfl_sync(0xFFFFFFFFu, bk, 0);
        #pragma unroll
        for (int off = 16; off; off >>= 1)
            cmx = fmaxf(cmx, __shfl_xor_sync(0xFFFFFFFFu, cmx, off));
        float s = 0.0f;
        #pragma unroll
        for (int j = 0; j < 32; j++)
            s += ex2((c[j] - cmx) * 7.2134752044448170f);   /* 5*log2(e) */
        #pragma unroll
        for (int off = 16; off; off >>= 1) s += __shfl_xor_sync(0xFFFFFFFFu, s, off);
        if (lane == 0) {
            g_idx[n] = bk;
            float lse = cmx * 5.0f + logf(s);
            float li  = ((const float*)row)[bk] * 5.0f;
            lsum += (double)(lse - li);
        }
    }
    if (lane == 0) lpart[warp] = lsum;
    __syncthreads();
    if (tid == 0) {
        double t = 0.0;
        for (int i = 0; i < 8; i++) t += lpart[i];
        atomicAdd(&g_loss, t);
    }
}

/* x_q gather, vectorized: 4 floats per thread */
__global__ void k_out4(const float* __restrict__ codebook,
                       float4* __restrict__ out4, int nvec) {
    int i = blockIdx.x * blockDim.x + threadIdx.x;
    if (i >= nvec) return;
    int n   = i >> 5;            /* 32 float4 per row */
    int col = (i & 31) * 4;
    const float* src = codebook + (size_t)g_idx[n] * 128 + col;
    out4[i] = make_float4(src[0], src[1], src[2], src[3]);
}

/* tail: loss + indices (+ scalar fallback for any unaligned remainder) */
__global__ void k_tail(const float* __restrict__ codebook,
                       float* __restrict__ out, int start, int out_size) {
    int i = start + blockIdx.x * blockDim.x + threadIdx.x;
    if (i >= out_size) return;
    if (i < ND) {
        int n = i >> 7;
        out[i] = codebook[(size_t)g_idx[n] * 128 + (i & 127)];
    } else if (i == ND) {
        out[i] = (float)(g_loss / 32768.0);
    } else {
        int j = i - ND - 1;
        out[i] = (j < N_PTS) ? (float)g_idx[j] : 0.0f;
    }
}

/* ---------------- launch ---------------------------------------------------- */
extern "C" void kernel_launch(void* const* d_in, const int* in_sizes, int n_in,
                              void* d_out, int out_size) {
    const float* x  = (const float*)d_in[0];
    const float* cb = (const float*)d_in[1];
    if (n_in >= 2 && in_sizes[0] == K_CB * D_DIM && in_sizes[1] == ND) {
        const float* t = x; x = cb; cb = t;
    }
    float* out = (float*)d_out;

    k_init<<<(K_CB + 255) / 256, 256>>>();
    k_norm<<<(K_CB * 32 + 255) / 256, 256>>>(cb, K_CB, 0);
    k_norm<<<(N_PTS * 32 + 255) / 256, 256>>>(x, N_PTS, 1);

    dim3 ggrid(K_CB / 128, N_PTS / 128);
    k_gemm<<<ggrid, 256>>>();
    k_pre<<<1, 1024>>>();

    k_u1<<<N_PTS / 64, 256>>>();        /* u1                  */
    k_la<<<1, 1024>>>(1, 0);            /* la1                 */
    k_lb<<<N_PTS / 32, 256>>>();        /* lb1                 */
    k_v<<<N_PTS / 64, 256>>>(1);        /* v2                  */
    k_la<<<1, 1024>>>(2, 0);            /* la2                 */
    k_lb<<<N_PTS / 32, 256>>>();        /* lb2                 */
    k_v<<<N_PTS / 64, 256>>>(2);        /* v3                  */
    k_la<<<1, 1024>>>(3, 1);            /* afix = la3 * 2^20   */

    k_argmax<<<N_PTS / 32, 256>>>();

    /* vectorized gather for the x_q segment, scalar tail for the rest */
    int nvec = (out_size < ND ? out_size : ND) / 4;
    if (nvec > 0)
        k_out4<<<(nvec + 255) / 256, 256>>>(cb, (float4*)out, nvec);
    int start = nvec * 4;
    int rem = out_size - start;
    if (rem > 0)
        k_tail<<<(rem + 255) / 256, 256>>>(cb, out, start, out_size);
}